// round 12
// baseline (speedup 1.0000x reference)
#include <cuda_runtime.h>
#include <cuda.h>
#include <cuda_fp16.h>
#include <cstdint>

// ---------------- problem constants ----------------
#define C_DIM  1024
#define MID    256
#define BATCH  16
#define HW     3136
#define TILE_M 128
#define NTILE  25          // ceil(3136/128)
#define KCH    64          // K elements per chunk

#define NC1 16             // stage1 K chunks (1024/64)
#define NC2 4              // stage2 (256/64)
#define NC3 16             // stage3: 4 oc blocks x 4 k chunks
#define NCTOT (NC1+NC2+NC3)

#define NTHREADS 1024
#define NWARPS   32

// ---------------- SMEM layout (bytes) ----------------
#define SM_FULL(j)  ((j)*8)               // 3 x full barriers
#define SM_EMPTY(j) (24 + (j)*8)          // 3 x empty barriers
#define SM_GG   128                       // 256 f32 relu(gate)
#define SM_B1   (SM_GG + 1024)
#define SM_B2   (SM_B1 + 1024)
#define SM_B3   (SM_B2 + 1024)            // 1024 f32
#define SM_A2   8192                      // 4 blocks x 16384: H1 / H2 (aliased)
#define SM_XH   (SM_A2 + 65536)           // 2 x 16384: stage-1 x fp16 K-major tiles
#define SM_BUFB (SM_XH + 2*16384)         // 3 x 32768  (weight tiles)
#define SM_TOTAL (SM_BUFB + 3*32768)      // 204800

// ---------------- device scratch ----------------
__device__ __align__(1024) __half g_W1h[MID * C_DIM];
__device__ __align__(1024) __half g_W2h[MID * MID];
__device__ __align__(1024) __half g_W3h[C_DIM * MID];

// ---------------- ptx helpers (generic PTX only, NO tcgen05) ------
__device__ __forceinline__ uint32_t smem_u32(const void* p) {
    uint32_t a;
    asm("{ .reg .u64 t; cvta.to.shared.u64 t, %1; cvt.u32.u64 %0, t; }" : "=r"(a) : "l"(p));
    return a;
}
#define SW128(bo) ((bo) ^ (((bo) >> 3) & 0x70))

#define MBAR_INIT(a, c) asm volatile("mbarrier.init.shared.b64 [%0], %1;" :: "r"(a), "r"(c) : "memory")
#define MBAR_EXPECT(a, b) asm volatile("mbarrier.arrive.expect_tx.shared.b64 _, [%0], %1;" :: "r"(a), "r"(b) : "memory")
#define MBAR_ARRIVE(a)  asm volatile("mbarrier.arrive.shared.b64 _, [%0];" :: "r"(a) : "memory")
#define MBAR_WAIT(a, p) do { \
    asm volatile("{\n\t.reg .pred P;\n\tWL_%=:\n\t" \
        "mbarrier.try_wait.parity.acquire.cta.shared::cta.b64 P, [%0], %1, 0x989680;\n\t" \
        "@!P bra WL_%=;\n\t}" :: "r"(a), "r"(p) : "memory"); } while (0)

#define TMA2D(sm, mp, cx, cy, mb) \
    asm volatile("cp.async.bulk.tensor.2d.shared::cta.global.tile.mbarrier::complete_tx::bytes " \
                 "[%0], [%1, {%2, %3}], [%4];" \
                 :: "r"(sm), "l"(mp), "r"(cx), "r"(cy), "r"(mb) : "memory")

#define LDSM4(r, addr) \
    asm volatile("ldmatrix.sync.aligned.m8n8.x4.shared.b16 {%0,%1,%2,%3}, [%4];" \
        : "=r"((r)[0]), "=r"((r)[1]), "=r"((r)[2]), "=r"((r)[3]) : "r"(addr))

#define LDSM4T(r, addr) \
    asm volatile("ldmatrix.sync.aligned.m8n8.x4.trans.shared.b16 {%0,%1,%2,%3}, [%4];" \
        : "=r"((r)[0]), "=r"((r)[1]), "=r"((r)[2]), "=r"((r)[3]) : "r"(addr))

#define MMA16816(d, a, b0, b1) \
    asm volatile("mma.sync.aligned.m16n8k16.row.col.f32.f16.f16.f32 " \
        "{%0,%1,%2,%3}, {%4,%5,%6,%7}, {%8,%9}, {%0,%1,%2,%3};" \
        : "+f"((d)[0]), "+f"((d)[1]), "+f"((d)[2]), "+f"((d)[3]) \
        : "r"((a)[0]), "r"((a)[1]), "r"((a)[2]), "r"((a)[3]), "r"(b0), "r"(b1))

#define STS32(a, v) asm volatile("st.shared.b32 [%0], %1;" :: "r"(a), "r"(v) : "memory")
#define STS64(a, v0, v1) asm volatile("st.shared.v2.b32 [%0], {%1, %2};" :: "r"(a), "r"(v0), "r"(v1) : "memory")

// ---------------- pre-pass: weights fp32 -> fp16 ----------------
__global__ void cvt_weights(const float* __restrict__ W1, const float* __restrict__ W2,
                            const float* __restrict__ W3) {
    int i = blockIdx.x * blockDim.x + threadIdx.x;
    if (i < MID * C_DIM) g_W1h[i] = __float2half_rn(W1[i]);
    if (i < MID * MID)   g_W2h[i] = __float2half_rn(W2[i]);
    if (i < C_DIM * MID) g_W3h[i] = __float2half_rn(W3[i]);
}

// ---------------- main fused kernel (32 warps, all compute) ----------------
__global__ void __launch_bounds__(NTHREADS, 1)
moe_main(const __grid_constant__ CUtensorMap mapW1,
         const __grid_constant__ CUtensorMap mapW2,
         const __grid_constant__ CUtensorMap mapW3,
         const float* __restrict__ x, const float* __restrict__ gate,
         const float* __restrict__ b1, const float* __restrict__ b2,
         const float* __restrict__ b3, float* __restrict__ out)
{
    extern __shared__ __align__(1024) char smem[];
    const uint32_t sb = smem_u32(smem);
    const int tid = threadIdx.x, wid = tid >> 5, lane = tid & 31;
    const int bt = blockIdx.y, nt = blockIdx.x;
    const int n0 = nt * TILE_M;

    const int M0 = (wid & 3) * 32;       // warp M block (4 in M: 128)
    const int N0 = (wid >> 2) * 32;      // warp N block (8 in N: 256)
    const int rowin = lane & 7, mat = lane >> 3;
    const uint32_t xorv = (uint32_t)rowin << 4;
    const uint32_t kA0 = ((uint32_t)((mat >> 1) * 16)) ^ xorv;   // + s*32 per step
    const uint32_t kB0 = ((uint32_t)((mat & 1) * 16)) ^ xorv;

    // non-trans ldmatrix addr parts (A [m][k] 128B rows, B [n][k] 128B rows)
    uint32_t aRow[2], bRow[2];
    #pragma unroll
    for (int t = 0; t < 2; t++) aRow[t] = (uint32_t)(M0 + t * 16 + (mat & 1) * 8 + rowin) * 128;
    #pragma unroll
    for (int p = 0; p < 2; p++) bRow[p] = (uint32_t)(N0 + p * 16 + (mat >> 1) * 8 + rowin) * 128;

    // trans ldmatrix addr parts for stage-1 A (xh [k][m] 256B rows)
    const uint32_t tRow = (uint32_t)((mat >> 1) * 8 + rowin);          // 0..15
    uint32_t tCol[2];
    #pragma unroll
    for (int t = 0; t < 2; t++)
        tCol[t] = ((uint32_t)((M0 + t * 16) * 2 + (mat & 1) * 16)) ^ xorv;

    if (tid == 0) {
        #pragma unroll
        for (int j = 0; j < 3; j++) { MBAR_INIT(sb + SM_FULL(j), 1); MBAR_INIT(sb + SM_EMPTY(j), NWARPS); }
    }
    __syncthreads();

    // stage biases / gate into smem
    float* gg  = (float*)(smem + SM_GG);
    float* b1s = (float*)(smem + SM_B1);
    float* b2s = (float*)(smem + SM_B2);
    float* b3s = (float*)(smem + SM_B3);
    if (tid < MID) {
        float g = gate[bt * MID + tid];
        gg[tid]  = g > 0.f ? g : 0.f;
        b1s[tid] = b1[tid];
        b2s[tid] = b2[tid];
    }
    if (tid < C_DIM) b3s[tid] = b3[tid];

    auto issue = [&](int ci) {
        int j = ci % 3;
        uint32_t fb = sb + SM_FULL(j);
        uint32_t bB = sb + SM_BUFB + j * 32768;
        MBAR_EXPECT(fb, 32768u);
        if (ci < NC1) {
            TMA2D(bB, (const void*)&mapW1, ci * KCH, 0, fb);
        } else if (ci < NC1 + NC2) {
            TMA2D(bB, (const void*)&mapW2, (ci - NC1) * KCH, 0, fb);
        } else {
            int t3 = ci - (NC1 + NC2), oc = t3 >> 2, kc = t3 & 3;
            TMA2D(bB, (const void*)&mapW3, kc * KCH, oc * 256, fb);
        }
    };
    if (tid == 0) { issue(0); issue(1); issue(2); }

    // ---- stage-1 x handling: direct LDG fp32 -> cvt -> xh fp16 [c][hw] ----
    const float* xsrc = x + (size_t)bt * C_DIM * HW + n0;
    const int lane4 = lane * 4;
    const bool xok = (n0 + lane4) < HW;    // float4 never straddles the edge (64-aligned)
    float4 xr[2];

    auto ldg_x = [&](int kc) {
        #pragma unroll
        for (int i = 0; i < 2; i++) {
            if (xok) {
                int c = kc * KCH + wid * 2 + i;
                xr[i] = *reinterpret_cast<const float4*>(xsrc + (size_t)c * HW + lane4);
            } else {
                xr[i] = make_float4(0.f, 0.f, 0.f, 0.f);
            }
        }
    };
    auto sts_x = [&](int buf) {
        uint32_t base = sb + SM_XH + buf * 16384;
        #pragma unroll
        for (int i = 0; i < 2; i++) {
            int r = wid * 2 + i;
            __half2 h0 = __floats2half2_rn(xr[i].x, xr[i].y);
            __half2 h1 = __floats2half2_rn(xr[i].z, xr[i].w);
            uint32_t bo = ((uint32_t)(lane * 8)) ^ (((uint32_t)(r & 7)) << 4);
            STS64(base + (uint32_t)r * 256 + bo, *(uint32_t*)&h0, *(uint32_t*)&h1);
        }
    };

    __syncthreads();   // gg/bias visible; barriers live before waits

    float acc[2][4][4];
    auto zero_acc = [&]() {
        #pragma unroll
        for (int t = 0; t < 2; t++)
            #pragma unroll
            for (int n = 0; n < 4; n++)
                #pragma unroll
                for (int q = 0; q < 4; q++) acc[t][n][q] = 0.f;
    };

    int fullp[3] = {0, 0, 0}, emptyp[3] = {0, 0, 0};

    // generic chunk: A via non-trans LDSM from aBase ([m][k] 128B rows)
    auto do_chunk = [&](int ci, uint32_t aBase) {
        int j = ci % 3;
        MBAR_WAIT(sb + SM_FULL(j), fullp[j]); fullp[j] ^= 1;
        uint32_t bBase = sb + SM_BUFB + j * 32768;
        #pragma unroll
        for (int s = 0; s < 4; s++) {
            uint32_t A[2][4], B[2][4];
            uint32_t ks = (uint32_t)(s * 32);
            #pragma unroll
            for (int t = 0; t < 2; t++) LDSM4(A[t], aBase + aRow[t] + (ks ^ kA0));
            #pragma unroll
            for (int p = 0; p < 2; p++) LDSM4(B[p], bBase + bRow[p] + (ks ^ kB0));
            #pragma unroll
            for (int t = 0; t < 2; t++)
                #pragma unroll
                for (int n = 0; n < 4; n++)
                    MMA16816(acc[t][n], A[t], B[n >> 1][(n & 1) * 2], B[n >> 1][(n & 1) * 2 + 1]);
        }
        if (lane == 0) MBAR_ARRIVE(sb + SM_EMPTY(j));
        if (tid == 0 && ci + 3 < NCTOT) {
            MBAR_WAIT(sb + SM_EMPTY(j), emptyp[j]); emptyp[j] ^= 1;
            issue(ci + 3);
        }
    };

    // stage-1 chunk: A via trans LDSM from xh buffer ([k][m] 256B rows)
    auto do_chunk_s1 = [&](int ci, int buf) {
        int j = ci % 3;
        MBAR_WAIT(sb + SM_FULL(j), fullp[j]); fullp[j] ^= 1;
        uint32_t bBase = sb + SM_BUFB + j * 32768;
        uint32_t xb = sb + SM_XH + buf * 16384;
        #pragma unroll
        for (int s = 0; s < 4; s++) {
            uint32_t A[2][4], B[2][4];
            uint32_t ks = (uint32_t)(s * 32);
            uint32_t rbase = xb + (uint32_t)(s * 16 + tRow) * 256;
            #pragma unroll
            for (int t = 0; t < 2; t++) LDSM4T(A[t], rbase + tCol[t]);
            #pragma unroll
            for (int p = 0; p < 2; p++) LDSM4(B[p], bBase + bRow[p] + (ks ^ kB0));
            #pragma unroll
            for (int t = 0; t < 2; t++)
                #pragma unroll
                for (int n = 0; n < 4; n++)
                    MMA16816(acc[t][n], A[t], B[n >> 1][(n & 1) * 2], B[n >> 1][(n & 1) * 2 + 1]);
        }
        if (lane == 0) MBAR_ARRIVE(sb + SM_EMPTY(j));
        if (tid == 0 && ci + 3 < NCTOT) {
            MBAR_WAIT(sb + SM_EMPTY(j), emptyp[j]); emptyp[j] ^= 1;
            issue(ci + 3);
        }
    };

    // gated-relu -> fp16 -> H (A2 region, SW128 per 64-col block, [m][k] layout)
    auto epi12 = [&](const float* __restrict__ bb) {
        #pragma unroll
        for (int n = 0; n < 4; n++) {
            int c = N0 + n * 8 + 2 * (lane & 3);
            float g0 = gg[c], g1 = gg[c + 1], q0 = bb[c], q1 = bb[c + 1];
            uint32_t base = sb + SM_A2 + (c >> 6) * 16384;
            uint32_t off = (uint32_t)(c & 63) * 2;
            #pragma unroll
            for (int t = 0; t < 2; t++) {
                int r = M0 + t * 16 + (lane >> 2);
                __half2 h0 = __floats2half2_rn(g0 * fmaxf(acc[t][n][0] + q0, 0.f),
                                               g1 * fmaxf(acc[t][n][1] + q1, 0.f));
                __half2 h1 = __floats2half2_rn(g0 * fmaxf(acc[t][n][2] + q0, 0.f),
                                               g1 * fmaxf(acc[t][n][3] + q1, 0.f));
                uint32_t bo0 = (uint32_t)r * 128 + off;
                uint32_t bo1 = (uint32_t)(r + 8) * 128 + off;
                STS32(base + SW128(bo0), *(uint32_t*)&h0);
                STS32(base + SW128(bo1), *(uint32_t*)&h1);
            }
        }
    };

    int ci = 0;

    // ---- stage 1: H1 = g*relu(W1 @ x + b1) ----
    zero_acc();
    ldg_x(0); sts_x(0);
    __syncthreads();
    for (int kc = 0; kc < NC1; kc++, ci++) {
        if (kc + 1 < NC1) ldg_x(kc + 1);           // LDG overlaps barrier wait + MMA
        do_chunk_s1(ci, kc & 1);
        if (kc + 1 < NC1) {
            sts_x((kc + 1) & 1);
            __syncthreads();                        // xh[(kc+1)&1] visible to all warps
        }
    }
    epi12(b1s);
    __syncthreads();

    // ---- stage 2: H2 = g*relu(W2 @ H1 + b2) ----
    zero_acc();
    for (int kc = 0; kc < NC2; kc++, ci++)
        do_chunk(ci, sb + SM_A2 + kc * 16384);
    __syncthreads();          // all H1 reads complete before H2 overwrites A2
    epi12(b2s);
    __syncthreads();

    // ---- stage 3: out = relu(W3 @ H2 + b3) + x ----
    for (int oc = 0; oc < 4; oc++) {
        zero_acc();
        for (int kc = 0; kc < 4; kc++, ci++)
            do_chunk(ci, sb + SM_A2 + kc * 16384);
        #pragma unroll
        for (int n = 0; n < 4; n++) {
            int ch = oc * 256 + N0 + n * 8 + 2 * (lane & 3);
            float q0 = b3s[ch], q1 = b3s[ch + 1];
            size_t gb = ((size_t)(bt * C_DIM + ch)) * HW;
            #pragma unroll
            for (int t = 0; t < 2; t++) {
                int r = M0 + t * 16 + (lane >> 2);
                int hw0 = n0 + r, hw1 = hw0 + 8;
                if (hw0 < HW) {
                    out[gb + hw0]      = fmaxf(acc[t][n][0] + q0, 0.f) + x[gb + hw0];
                    out[gb + HW + hw0] = fmaxf(acc[t][n][1] + q1, 0.f) + x[gb + HW + hw0];
                }
                if (hw1 < HW) {
                    out[gb + hw1]      = fmaxf(acc[t][n][2] + q0, 0.f) + x[gb + hw1];
                    out[gb + HW + hw1] = fmaxf(acc[t][n][3] + q1, 0.f) + x[gb + HW + hw1];
                }
            }
        }
    }
}

// ---------------- host side ----------------
typedef CUresult (*PFN_Encode)(CUtensorMap*, CUtensorMapDataType, cuuint32_t, void*,
                               const cuuint64_t*, const cuuint64_t*, const cuuint32_t*,
                               const cuuint32_t*, CUtensorMapInterleave, CUtensorMapSwizzle,
                               CUtensorMapL2promotion, CUtensorMapFloatOOBfill);

static PFN_Encode get_encode_fn() {
    static PFN_Encode fn = nullptr;
    if (!fn) {
        cudaDriverEntryPointQueryResult st;
#if CUDART_VERSION >= 12050
        cudaGetDriverEntryPointByVersion("cuTensorMapEncodeTiled", (void**)&fn, 12000,
                                         cudaEnableDefault, &st);
#else
        cudaGetDriverEntryPoint("cuTensorMapEncodeTiled", (void**)&fn, cudaEnableDefault, &st);
#endif
    }
    return fn;
}

static void make_map(CUtensorMap* m, void* base, uint64_t d0, uint64_t d1,
                     uint64_t rowstride_bytes, uint32_t box0, uint32_t box1) {
    cuuint64_t dims[2] = {d0, d1};
    cuuint64_t strides[1] = {rowstride_bytes};
    cuuint32_t box[2] = {box0, box1};
    cuuint32_t es[2] = {1, 1};
    get_encode_fn()(m, CU_TENSOR_MAP_DATA_TYPE_FLOAT16, 2, base, dims, strides, box, es,
                    CU_TENSOR_MAP_INTERLEAVE_NONE, CU_TENSOR_MAP_SWIZZLE_128B,
                    CU_TENSOR_MAP_L2_PROMOTION_L2_128B, CU_TENSOR_MAP_FLOAT_OOB_FILL_NONE);
}

extern "C" void kernel_launch(void* const* d_in, const int* in_sizes, int n_in,
                              void* d_out, int out_size)
{
    const float* x    = (const float*)d_in[0];
    const float* gate = (const float*)d_in[1];
    const float* W1   = (const float*)d_in[2];
    const float* b1   = (const float*)d_in[3];
    const float* W2   = (const float*)d_in[4];
    const float* b2   = (const float*)d_in[5];
    const float* W3   = (const float*)d_in[6];
    const float* b3   = (const float*)d_in[7];
    float* out        = (float*)d_out;

    void *pW1, *pW2, *pW3;
    cudaGetSymbolAddress(&pW1, g_W1h);
    cudaGetSymbolAddress(&pW2, g_W2h);
    cudaGetSymbolAddress(&pW3, g_W3h);

    CUtensorMap m1, m2, m3;
    make_map(&m1, pW1, C_DIM, MID,   C_DIM * 2, KCH, 256);
    make_map(&m2, pW2, MID,   MID,   MID * 2,   KCH, 256);
    make_map(&m3, pW3, MID,   C_DIM, MID * 2,   KCH, 256);

    cvt_weights<<<(MID * C_DIM + 255) / 256, 256>>>(W1, W2, W3);

    cudaFuncSetAttribute(moe_main, cudaFuncAttributeMaxDynamicSharedMemorySize, SM_TOTAL);
    dim3 grid(NTILE, BATCH);
    moe_main<<<grid, NTHREADS, SM_TOTAL>>>(m1, m2, m3, x, gate, b1, b2, b3, out);
}

// round 13
// speedup vs baseline: 1.1733x; 1.1733x over previous
#include <cuda_runtime.h>
#include <cuda.h>
#include <cuda_fp16.h>
#include <cstdint>

// ---------------- problem constants ----------------
#define C_DIM  1024
#define MID    256
#define BATCH  16
#define HW     3136
#define TILE_M 128
#define NTILE  25          // ceil(3136/128)
#define KCH    64          // K elements per chunk

#define NC1 16             // stage1 K chunks (1024/64)
#define NC2 4              // stage2 (256/64)
#define NC3 16             // stage3: 4 oc blocks x 4 k chunks
#define NCTOT (NC1+NC2+NC3)

#define NTHREADS 512
#define NWARPS   16
#define NSTAGE   4

// ---------------- SMEM layout (bytes) ----------------
#define SM_FULL(j)  ((j)*8)               // 4 x full barriers
#define SM_EMPTY(j) (32 + (j)*8)          // 4 x empty barriers
#define SM_GG   128                       // 256 f32 relu(gate)
#define SM_B1   (SM_GG + 1024)
#define SM_B2   (SM_B1 + 1024)
#define SM_B3   (SM_B2 + 1024)            // 1024 f32
#define SM_A2   8192                      // 4 blocks x 16384: H1 / H2 (aliased)
#define SM_XH   (SM_A2 + 32768)           // ALIAS: x fp16 staging in A2 blocks 2,3 (dead until epi12)
#define SM_BUFB (SM_A2 + 65536)           // 4 x 32768  (weight tiles)
#define SM_TOTAL (SM_BUFB + NSTAGE*32768) // 204800

// ---------------- device scratch ----------------
__device__ __align__(1024) __half g_W1h[MID * C_DIM];
__device__ __align__(1024) __half g_W2h[MID * MID];
__device__ __align__(1024) __half g_W3h[C_DIM * MID];

// ---------------- ptx helpers (generic PTX only, NO tcgen05) ------
__device__ __forceinline__ uint32_t smem_u32(const void* p) {
    uint32_t a;
    asm("{ .reg .u64 t; cvta.to.shared.u64 t, %1; cvt.u32.u64 %0, t; }" : "=r"(a) : "l"(p));
    return a;
}
#define SW128(bo) ((bo) ^ (((bo) >> 3) & 0x70))

#define MBAR_INIT(a, c) asm volatile("mbarrier.init.shared.b64 [%0], %1;" :: "r"(a), "r"(c) : "memory")
#define MBAR_EXPECT(a, b) asm volatile("mbarrier.arrive.expect_tx.shared.b64 _, [%0], %1;" :: "r"(a), "r"(b) : "memory")
#define MBAR_ARRIVE(a)  asm volatile("mbarrier.arrive.shared.b64 _, [%0];" :: "r"(a) : "memory")
#define MBAR_WAIT(a, p) do { \
    asm volatile("{\n\t.reg .pred P;\n\tWL_%=:\n\t" \
        "mbarrier.try_wait.parity.acquire.cta.shared::cta.b64 P, [%0], %1, 0x989680;\n\t" \
        "@!P bra WL_%=;\n\t}" :: "r"(a), "r"(p) : "memory"); } while (0)

#define TMA2D(sm, mp, cx, cy, mb) \
    asm volatile("cp.async.bulk.tensor.2d.shared::cta.global.tile.mbarrier::complete_tx::bytes " \
                 "[%0], [%1, {%2, %3}], [%4];" \
                 :: "r"(sm), "l"(mp), "r"(cx), "r"(cy), "r"(mb) : "memory")

#define LDSM4(r, addr) \
    asm volatile("ldmatrix.sync.aligned.m8n8.x4.shared.b16 {%0,%1,%2,%3}, [%4];" \
        : "=r"((r)[0]), "=r"((r)[1]), "=r"((r)[2]), "=r"((r)[3]) : "r"(addr))

#define LDSM4T(r, addr) \
    asm volatile("ldmatrix.sync.aligned.m8n8.x4.trans.shared.b16 {%0,%1,%2,%3}, [%4];" \
        : "=r"((r)[0]), "=r"((r)[1]), "=r"((r)[2]), "=r"((r)[3]) : "r"(addr))

#define MMA16816(d, a, b0, b1) \
    asm volatile("mma.sync.aligned.m16n8k16.row.col.f32.f16.f16.f32 " \
        "{%0,%1,%2,%3}, {%4,%5,%6,%7}, {%8,%9}, {%0,%1,%2,%3};" \
        : "+f"((d)[0]), "+f"((d)[1]), "+f"((d)[2]), "+f"((d)[3]) \
        : "r"((a)[0]), "r"((a)[1]), "r"((a)[2]), "r"((a)[3]), "r"(b0), "r"(b1))

#define STS32(a, v) asm volatile("st.shared.b32 [%0], %1;" :: "r"(a), "r"(v) : "memory")
#define STS64(a, v0, v1) asm volatile("st.shared.v2.b32 [%0], {%1, %2};" :: "r"(a), "r"(v0), "r"(v1) : "memory")

// ---------------- pre-pass: weights fp32 -> fp16 ----------------
__global__ void cvt_weights(const float* __restrict__ W1, const float* __restrict__ W2,
                            const float* __restrict__ W3) {
    int i = blockIdx.x * blockDim.x + threadIdx.x;
    if (i < MID * C_DIM) g_W1h[i] = __float2half_rn(W1[i]);
    if (i < MID * MID)   g_W2h[i] = __float2half_rn(W2[i]);
    if (i < C_DIM * MID) g_W3h[i] = __float2half_rn(W3[i]);
}

// ---------------- main fused kernel (16 warps, all compute) ----------------
__global__ void __launch_bounds__(NTHREADS, 1)
moe_main(const __grid_constant__ CUtensorMap mapW1,
         const __grid_constant__ CUtensorMap mapW2,
         const __grid_constant__ CUtensorMap mapW3,
         const float* __restrict__ x, const float* __restrict__ gate,
         const float* __restrict__ b1, const float* __restrict__ b2,
         const float* __restrict__ b3, float* __restrict__ out)
{
    extern __shared__ __align__(1024) char smem[];
    const uint32_t sb = smem_u32(smem);
    const int tid = threadIdx.x, wid = tid >> 5, lane = tid & 31;
    const int bt = blockIdx.y, nt = blockIdx.x;
    const int n0 = nt * TILE_M;

    const int M0 = (wid & 1) * 64;       // warp M block (2 in M: 128)
    const int N0 = (wid >> 1) * 32;      // warp N block (8 in N: 256)
    const int rowin = lane & 7, mat = lane >> 3;
    const uint32_t xorv = (uint32_t)rowin << 4;

    // non-trans ldmatrix addr parts (A [m][k] 128B rows, B [n][k] 128B rows)
    uint32_t aRow[4], bRow[2], kAo[4], kBo[4];
    #pragma unroll
    for (int t = 0; t < 4; t++) aRow[t] = (uint32_t)(M0 + t * 16 + (mat & 1) * 8 + rowin) * 128;
    #pragma unroll
    for (int p = 0; p < 2; p++) bRow[p] = (uint32_t)(N0 + p * 16 + (mat >> 1) * 8 + rowin) * 128;
    #pragma unroll
    for (int s = 0; s < 4; s++) {
        kAo[s] = ((uint32_t)(s * 32 + (mat >> 1) * 16)) ^ xorv;
        kBo[s] = ((uint32_t)(s * 32 + (mat & 1) * 16)) ^ xorv;
    }

    // trans ldmatrix addr parts for stage-1 A (xh [k][m] 256B rows)
    const uint32_t tRow = (uint32_t)((mat >> 1) * 8 + rowin);          // 0..15
    uint32_t tCol[4];
    #pragma unroll
    for (int t = 0; t < 4; t++)
        tCol[t] = ((uint32_t)((M0 + t * 16) * 2 + (mat & 1) * 16)) ^ xorv;

    if (tid == 0) {
        #pragma unroll
        for (int j = 0; j < NSTAGE; j++) { MBAR_INIT(sb + SM_FULL(j), 1); MBAR_INIT(sb + SM_EMPTY(j), NWARPS); }
    }
    __syncthreads();

    // stage biases / gate into smem
    float* gg  = (float*)(smem + SM_GG);
    float* b1s = (float*)(smem + SM_B1);
    float* b2s = (float*)(smem + SM_B2);
    float* b3s = (float*)(smem + SM_B3);
    for (int i = tid; i < MID; i += NTHREADS) {
        float g = gate[bt * MID + i];
        gg[i]  = g > 0.f ? g : 0.f;
        b1s[i] = b1[i];
        b2s[i] = b2[i];
    }
    for (int i = tid; i < C_DIM; i += NTHREADS) b3s[i] = b3[i];

    auto issue = [&](int ci) {
        int j = ci % NSTAGE;
        uint32_t fb = sb + SM_FULL(j);
        uint32_t bB = sb + SM_BUFB + j * 32768;
        MBAR_EXPECT(fb, 32768u);
        if (ci < NC1) {
            TMA2D(bB, (const void*)&mapW1, ci * KCH, 0, fb);
        } else if (ci < NC1 + NC2) {
            TMA2D(bB, (const void*)&mapW2, (ci - NC1) * KCH, 0, fb);
        } else {
            int t3 = ci - (NC1 + NC2), oc = t3 >> 2, kc = t3 & 3;
            TMA2D(bB, (const void*)&mapW3, kc * KCH, oc * 256, fb);
        }
    };
    if (tid == 0) { issue(0); issue(1); issue(2); }

    // ---- stage-1 x handling: direct LDG fp32 -> cvt -> xh fp16 [c][hw] ----
    const float* xsrc = x + (size_t)bt * C_DIM * HW + n0;
    const int lane4 = lane * 4;
    const bool xok = (n0 + lane4) < HW;    // float4 never straddles the edge (64-aligned)
    float4 xr[4];

    auto ldg_x = [&](int kc) {
        #pragma unroll
        for (int i = 0; i < 4; i++) {
            if (xok) {
                int c = kc * KCH + wid * 4 + i;
                xr[i] = *reinterpret_cast<const float4*>(xsrc + (size_t)c * HW + lane4);
            } else {
                xr[i] = make_float4(0.f, 0.f, 0.f, 0.f);
            }
        }
    };
    auto sts_x = [&](int buf) {
        uint32_t base = sb + SM_XH + buf * 16384;
        #pragma unroll
        for (int i = 0; i < 4; i++) {
            int r = wid * 4 + i;
            __half2 h0 = __floats2half2_rn(xr[i].x, xr[i].y);
            __half2 h1 = __floats2half2_rn(xr[i].z, xr[i].w);
            uint32_t bo = ((uint32_t)(lane * 8)) ^ (((uint32_t)(r & 7)) << 4);
            STS64(base + (uint32_t)r * 256 + bo, *(uint32_t*)&h0, *(uint32_t*)&h1);
        }
    };

    __syncthreads();   // gg/bias visible; barriers live before waits

    float acc[4][4][4];
    auto zero_acc = [&]() {
        #pragma unroll
        for (int t = 0; t < 4; t++)
            #pragma unroll
            for (int n = 0; n < 4; n++)
                #pragma unroll
                for (int q = 0; q < 4; q++) acc[t][n][q] = 0.f;
    };

    int fullp[NSTAGE] = {0, 0, 0, 0}, emptyp[NSTAGE] = {0, 0, 0, 0};

    // generic chunk: A via non-trans LDSM from aBase ([m][k] 128B rows)
    auto do_chunk = [&](int ci, uint32_t aBase) {
        int j = ci % NSTAGE;
        MBAR_WAIT(sb + SM_FULL(j), fullp[j]); fullp[j] ^= 1;
        uint32_t bBase = sb + SM_BUFB + j * 32768;
        #pragma unroll
        for (int s = 0; s < 4; s++) {
            uint32_t A[4][4], B[2][4];
            #pragma unroll
            for (int t = 0; t < 4; t++) LDSM4(A[t], aBase + aRow[t] + kAo[s]);
            #pragma unroll
            for (int p = 0; p < 2; p++) LDSM4(B[p], bBase + bRow[p] + kBo[s]);
            #pragma unroll
            for (int t = 0; t < 4; t++)
                #pragma unroll
                for (int n = 0; n < 4; n++)
                    MMA16816(acc[t][n], A[t], B[n >> 1][(n & 1) * 2], B[n >> 1][(n & 1) * 2 + 1]);
        }
        if (lane == 0) MBAR_ARRIVE(sb + SM_EMPTY(j));
        if (tid == 0 && ci + 3 < NCTOT) {
            int jb = (ci + 3) % NSTAGE;
            MBAR_WAIT(sb + SM_EMPTY(j), emptyp[j]); emptyp[j] ^= 1;
            (void)jb;
            issue(ci + 3);
        }
    };

    // stage-1 chunk: A via trans LDSM from xh buffer ([k][m] 256B rows)
    auto do_chunk_s1 = [&](int ci, int buf) {
        int j = ci % NSTAGE;
        MBAR_WAIT(sb + SM_FULL(j), fullp[j]); fullp[j] ^= 1;
        uint32_t bBase = sb + SM_BUFB + j * 32768;
        uint32_t xb = sb + SM_XH + buf * 16384;
        #pragma unroll
        for (int s = 0; s < 4; s++) {
            uint32_t A[4][4], B[2][4];
            uint32_t rbase = xb + (uint32_t)(s * 16 + tRow) * 256;
            #pragma unroll
            for (int t = 0; t < 4; t++) LDSM4T(A[t], rbase + tCol[t]);
            #pragma unroll
            for (int p = 0; p < 2; p++) LDSM4(B[p], bBase + bRow[p] + kBo[s]);
            #pragma unroll
            for (int t = 0; t < 4; t++)
                #pragma unroll
                for (int n = 0; n < 4; n++)
                    MMA16816(acc[t][n], A[t], B[n >> 1][(n & 1) * 2], B[n >> 1][(n & 1) * 2 + 1]);
        }
        if (lane == 0) MBAR_ARRIVE(sb + SM_EMPTY(j));
        if (tid == 0 && ci + 3 < NCTOT) {
            MBAR_WAIT(sb + SM_EMPTY(j), emptyp[j]); emptyp[j] ^= 1;
            issue(ci + 3);
        }
    };

    // gated-relu -> fp16 -> H (A2 region, SW128 per 64-col block, [m][k] layout)
    auto epi12 = [&](const float* __restrict__ bb) {
        #pragma unroll
        for (int n = 0; n < 4; n++) {
            int c = N0 + n * 8 + 2 * (lane & 3);
            float g0 = gg[c], g1 = gg[c + 1], q0 = bb[c], q1 = bb[c + 1];
            uint32_t base = sb + SM_A2 + (c >> 6) * 16384;
            uint32_t off = (uint32_t)(c & 63) * 2;
            #pragma unroll
            for (int t = 0; t < 4; t++) {
                int r = M0 + t * 16 + (lane >> 2);
                __half2 h0 = __floats2half2_rn(g0 * fmaxf(acc[t][n][0] + q0, 0.f),
                                               g1 * fmaxf(acc[t][n][1] + q1, 0.f));
                __half2 h1 = __floats2half2_rn(g0 * fmaxf(acc[t][n][2] + q0, 0.f),
                                               g1 * fmaxf(acc[t][n][3] + q1, 0.f));
                uint32_t bo0 = (uint32_t)r * 128 + off;
                uint32_t bo1 = (uint32_t)(r + 8) * 128 + off;
                STS32(base + SW128(bo0), *(uint32_t*)&h0);
                STS32(base + SW128(bo1), *(uint32_t*)&h1);
            }
        }
    };

    int ci = 0;

    // ---- stage 1: H1 = g*relu(W1 @ x + b1) ----
    zero_acc();
    ldg_x(0); sts_x(0);
    __syncthreads();
    for (int kc = 0; kc < NC1; kc++, ci++) {
        if (kc + 1 < NC1) ldg_x(kc + 1);           // LDG overlaps barrier wait + MMA
        do_chunk_s1(ci, kc & 1);
        if (kc + 1 < NC1) {
            sts_x((kc + 1) & 1);
            __syncthreads();                        // xh[(kc+1)&1] visible to all warps
        }
    }
    __syncthreads();          // all XH reads done before epi12 overwrites alias (A2 blocks 2,3)
    epi12(b1s);
    __syncthreads();

    // ---- stage 2: H2 = g*relu(W2 @ H1 + b2) ----
    zero_acc();
    for (int kc = 0; kc < NC2; kc++, ci++)
        do_chunk(ci, sb + SM_A2 + kc * 16384);
    __syncthreads();          // all H1 reads complete before H2 overwrites A2
    epi12(b2s);
    __syncthreads();

    // ---- stage 3: out = relu(W3 @ H2 + b3) + x ----
    for (int oc = 0; oc < 4; oc++) {
        zero_acc();
        for (int kc = 0; kc < 4; kc++, ci++)
            do_chunk(ci, sb + SM_A2 + kc * 16384);
        #pragma unroll
        for (int n = 0; n < 4; n++) {
            int ch = oc * 256 + N0 + n * 8 + 2 * (lane & 3);
            float q0 = b3s[ch], q1 = b3s[ch + 1];
            size_t gb = ((size_t)(bt * C_DIM + ch)) * HW;
            #pragma unroll
            for (int t = 0; t < 4; t++) {
                int r = M0 + t * 16 + (lane >> 2);
                int hw0 = n0 + r, hw1 = hw0 + 8;
                if (hw0 < HW) {
                    out[gb + hw0]      = fmaxf(acc[t][n][0] + q0, 0.f) + x[gb + hw0];
                    out[gb + HW + hw0] = fmaxf(acc[t][n][1] + q1, 0.f) + x[gb + HW + hw0];
                }
                if (hw1 < HW) {
                    out[gb + hw1]      = fmaxf(acc[t][n][2] + q0, 0.f) + x[gb + hw1];
                    out[gb + HW + hw1] = fmaxf(acc[t][n][3] + q1, 0.f) + x[gb + HW + hw1];
                }
            }
        }
    }
}

// ---------------- host side ----------------
typedef CUresult (*PFN_Encode)(CUtensorMap*, CUtensorMapDataType, cuuint32_t, void*,
                               const cuuint64_t*, const cuuint64_t*, const cuuint32_t*,
                               const cuuint32_t*, CUtensorMapInterleave, CUtensorMapSwizzle,
                               CUtensorMapL2promotion, CUtensorMapFloatOOBfill);

static PFN_Encode get_encode_fn() {
    static PFN_Encode fn = nullptr;
    if (!fn) {
        cudaDriverEntryPointQueryResult st;
#if CUDART_VERSION >= 12050
        cudaGetDriverEntryPointByVersion("cuTensorMapEncodeTiled", (void**)&fn, 12000,
                                         cudaEnableDefault, &st);
#else
        cudaGetDriverEntryPoint("cuTensorMapEncodeTiled", (void**)&fn, cudaEnableDefault, &st);
#endif
    }
    return fn;
}

static void make_map(CUtensorMap* m, void* base, uint64_t d0, uint64_t d1,
                     uint64_t rowstride_bytes, uint32_t box0, uint32_t box1) {
    cuuint64_t dims[2] = {d0, d1};
    cuuint64_t strides[1] = {rowstride_bytes};
    cuuint32_t box[2] = {box0, box1};
    cuuint32_t es[2] = {1, 1};
    get_encode_fn()(m, CU_TENSOR_MAP_DATA_TYPE_FLOAT16, 2, base, dims, strides, box, es,
                    CU_TENSOR_MAP_INTERLEAVE_NONE, CU_TENSOR_MAP_SWIZZLE_128B,
                    CU_TENSOR_MAP_L2_PROMOTION_L2_128B, CU_TENSOR_MAP_FLOAT_OOB_FILL_NONE);
}

extern "C" void kernel_launch(void* const* d_in, const int* in_sizes, int n_in,
                              void* d_out, int out_size)
{
    const float* x    = (const float*)d_in[0];
    const float* gate = (const float*)d_in[1];
    const float* W1   = (const float*)d_in[2];
    const float* b1   = (const float*)d_in[3];
    const float* W2   = (const float*)d_in[4];
    const float* b2   = (const float*)d_in[5];
    const float* W3   = (const float*)d_in[6];
    const float* b3   = (const float*)d_in[7];
    float* out        = (float*)d_out;

    void *pW1, *pW2, *pW3;
    cudaGetSymbolAddress(&pW1, g_W1h);
    cudaGetSymbolAddress(&pW2, g_W2h);
    cudaGetSymbolAddress(&pW3, g_W3h);

    CUtensorMap m1, m2, m3;
    make_map(&m1, pW1, C_DIM, MID,   C_DIM * 2, KCH, 256);
    make_map(&m2, pW2, MID,   MID,   MID * 2,   KCH, 256);
    make_map(&m3, pW3, MID,   C_DIM, MID * 2,   KCH, 256);

    cvt_weights<<<(MID * C_DIM + 255) / 256, 256>>>(W1, W2, W3);

    cudaFuncSetAttribute(moe_main, cudaFuncAttributeMaxDynamicSharedMemorySize, SM_TOTAL);
    dim3 grid(NTILE, BATCH);
    moe_main<<<grid, NTHREADS, SM_TOTAL>>>(m1, m2, m3, x, gate, b1, b2, b3, out);
}

// round 14
// speedup vs baseline: 1.4494x; 1.2353x over previous
#include <cuda_runtime.h>
#include <cuda.h>
#include <cuda_fp16.h>
#include <cstdint>

// ---------------- problem constants ----------------
#define C_DIM  1024
#define MID    256
#define BATCH  16
#define HW     3136
#define TILE_M 64
#define NTILE  49          // 3136/64 exact -> no edge guards
#define KCH    64          // K elements per chunk

#define NC1 16             // stage1 K chunks (1024/64)
#define NC2 4              // stage2 (256/64)
#define NC3 16             // stage3: 4 oc blocks x 4 k chunks
#define NCTOT (NC1+NC2+NC3)

#define NTHREADS 256
#define NWARPS   8
#define NSTAGE   2

// ---------------- SMEM layout (bytes) ----------------
#define SM_FULL(j)  ((j)*8)               // 2 x full barriers
#define SM_EMPTY(j) (16 + (j)*8)          // 2 x empty barriers
#define SM_GG   128                       // 256 f32 relu(gate)
#define SM_B1   (SM_GG + 1024)
#define SM_B2   (SM_B1 + 1024)
#define SM_B3   (SM_B2 + 1024)            // 1024 f32
#define SM_A2   8192                      // 4 blocks x 8192: H1/H2 [64m][64k] (aliased)
#define SM_XH   (SM_A2 + 16384)           // ALIAS: x fp16 staging in A2 blocks 2,3
#define SM_BUFB (SM_A2 + 32768)           // 2 x 32768 (weight tiles [256n][64k])
#define SM_TOTAL (SM_BUFB + NSTAGE*32768) // 106496 (104 KB) -> 2 CTAs/SM

// ---------------- device scratch ----------------
__device__ __align__(1024) __half g_W1h[MID * C_DIM];
__device__ __align__(1024) __half g_W2h[MID * MID];
__device__ __align__(1024) __half g_W3h[C_DIM * MID];

// ---------------- ptx helpers (generic PTX only, NO tcgen05) ------
__device__ __forceinline__ uint32_t smem_u32(const void* p) {
    uint32_t a;
    asm("{ .reg .u64 t; cvta.to.shared.u64 t, %1; cvt.u32.u64 %0, t; }" : "=r"(a) : "l"(p));
    return a;
}
#define SW128(bo) ((bo) ^ (((bo) >> 3) & 0x70))

#define MBAR_INIT(a, c) asm volatile("mbarrier.init.shared.b64 [%0], %1;" :: "r"(a), "r"(c) : "memory")
#define MBAR_EXPECT(a, b) asm volatile("mbarrier.arrive.expect_tx.shared.b64 _, [%0], %1;" :: "r"(a), "r"(b) : "memory")
#define MBAR_ARRIVE(a)  asm volatile("mbarrier.arrive.shared.b64 _, [%0];" :: "r"(a) : "memory")
#define MBAR_WAIT(a, p) do { \
    asm volatile("{\n\t.reg .pred P;\n\tWL_%=:\n\t" \
        "mbarrier.try_wait.parity.acquire.cta.shared::cta.b64 P, [%0], %1, 0x989680;\n\t" \
        "@!P bra WL_%=;\n\t}" :: "r"(a), "r"(p) : "memory"); } while (0)

#define TMA2D(sm, mp, cx, cy, mb) \
    asm volatile("cp.async.bulk.tensor.2d.shared::cta.global.tile.mbarrier::complete_tx::bytes " \
                 "[%0], [%1, {%2, %3}], [%4];" \
                 :: "r"(sm), "l"(mp), "r"(cx), "r"(cy), "r"(mb) : "memory")

#define LDSM4(r, addr) \
    asm volatile("ldmatrix.sync.aligned.m8n8.x4.shared.b16 {%0,%1,%2,%3}, [%4];" \
        : "=r"((r)[0]), "=r"((r)[1]), "=r"((r)[2]), "=r"((r)[3]) : "r"(addr))

#define LDSM4T(r, addr) \
    asm volatile("ldmatrix.sync.aligned.m8n8.x4.trans.shared.b16 {%0,%1,%2,%3}, [%4];" \
        : "=r"((r)[0]), "=r"((r)[1]), "=r"((r)[2]), "=r"((r)[3]) : "r"(addr))

#define MMA16816(d, a, b0, b1) \
    asm volatile("mma.sync.aligned.m16n8k16.row.col.f32.f16.f16.f32 " \
        "{%0,%1,%2,%3}, {%4,%5,%6,%7}, {%8,%9}, {%0,%1,%2,%3};" \
        : "+f"((d)[0]), "+f"((d)[1]), "+f"((d)[2]), "+f"((d)[3]) \
        : "r"((a)[0]), "r"((a)[1]), "r"((a)[2]), "r"((a)[3]), "r"(b0), "r"(b1))

#define STS32(a, v) asm volatile("st.shared.b32 [%0], %1;" :: "r"(a), "r"(v) : "memory")
#define STS64(a, v0, v1) asm volatile("st.shared.v2.b32 [%0], {%1, %2};" :: "r"(a), "r"(v0), "r"(v1) : "memory")

// ---------------- pre-pass: weights fp32 -> fp16 ----------------
__global__ void cvt_weights(const float* __restrict__ W1, const float* __restrict__ W2,
                            const float* __restrict__ W3) {
    int i = blockIdx.x * blockDim.x + threadIdx.x;
    if (i < MID * C_DIM) g_W1h[i] = __float2half_rn(W1[i]);
    if (i < MID * MID)   g_W2h[i] = __float2half_rn(W2[i]);
    if (i < C_DIM * MID) g_W3h[i] = __float2half_rn(W3[i]);
}

// ---------------- main fused kernel (8 warps, 2 CTAs/SM) ----------------
__global__ void __launch_bounds__(NTHREADS, 2)
moe_main(const __grid_constant__ CUtensorMap mapW1,
         const __grid_constant__ CUtensorMap mapW2,
         const __grid_constant__ CUtensorMap mapW3,
         const float* __restrict__ x, const float* __restrict__ gate,
         const float* __restrict__ b1, const float* __restrict__ b2,
         const float* __restrict__ b3, float* __restrict__ out)
{
    extern __shared__ __align__(1024) char smem[];
    const uint32_t sb = smem_u32(smem);
    const int tid = threadIdx.x, wid = tid >> 5, lane = tid & 31;
    const int bt = blockIdx.y, nt = blockIdx.x;
    const int n0 = nt * TILE_M;

    const int N0 = wid * 32;             // warp N block (8 in N: 256); M covers all 64
    const int rowin = lane & 7, mat = lane >> 3;
    const uint32_t xorv = (uint32_t)rowin << 4;

    // non-trans ldmatrix addr parts (A [m][k] 128B rows, B [n][k] 128B rows)
    uint32_t aRow[4], bRow[2], kAo[4], kBo[4];
    #pragma unroll
    for (int t = 0; t < 4; t++) aRow[t] = (uint32_t)(t * 16 + (mat & 1) * 8 + rowin) * 128;
    #pragma unroll
    for (int p = 0; p < 2; p++) bRow[p] = (uint32_t)(N0 + p * 16 + (mat >> 1) * 8 + rowin) * 128;
    #pragma unroll
    for (int s = 0; s < 4; s++) {
        kAo[s] = ((uint32_t)(s * 32 + (mat >> 1) * 16)) ^ xorv;
        kBo[s] = ((uint32_t)(s * 32 + (mat & 1) * 16)) ^ xorv;
    }

    // trans ldmatrix addr parts for stage-1 A (xh [k][m] 128B rows)
    const uint32_t tRow = (uint32_t)((mat >> 1) * 8 + rowin);          // 0..15
    uint32_t tCol[4];
    #pragma unroll
    for (int t = 0; t < 4; t++)
        tCol[t] = ((uint32_t)((t * 16) * 2 + (mat & 1) * 16)) ^ xorv;

    if (tid == 0) {
        #pragma unroll
        for (int j = 0; j < NSTAGE; j++) { MBAR_INIT(sb + SM_FULL(j), 1); MBAR_INIT(sb + SM_EMPTY(j), NWARPS); }
    }
    __syncthreads();

    // stage biases / gate into smem
    float* gg  = (float*)(smem + SM_GG);
    float* b1s = (float*)(smem + SM_B1);
    float* b2s = (float*)(smem + SM_B2);
    float* b3s = (float*)(smem + SM_B3);
    for (int i = tid; i < MID; i += NTHREADS) {
        float g = gate[bt * MID + i];
        gg[i]  = g > 0.f ? g : 0.f;
        b1s[i] = b1[i];
        b2s[i] = b2[i];
    }
    for (int i = tid; i < C_DIM; i += NTHREADS) b3s[i] = b3[i];

    auto issue = [&](int ci) {
        int j = ci & (NSTAGE - 1);
        uint32_t fb = sb + SM_FULL(j);
        uint32_t bB = sb + SM_BUFB + j * 32768;
        MBAR_EXPECT(fb, 32768u);
        if (ci < NC1) {
            TMA2D(bB, (const void*)&mapW1, ci * KCH, 0, fb);
        } else if (ci < NC1 + NC2) {
            TMA2D(bB, (const void*)&mapW2, (ci - NC1) * KCH, 0, fb);
        } else {
            int t3 = ci - (NC1 + NC2), oc = t3 >> 2, kc = t3 & 3;
            TMA2D(bB, (const void*)&mapW3, kc * KCH, oc * 256, fb);
        }
    };
    if (tid == 0) { issue(0); issue(1); }

    // ---- stage-1 x: LDG fp32 -> cvt -> xh fp16 [k][m] (64x64, 128B rows) ----
    // thread: kq = tid>>4 (0..15), mq = tid&15; round i: k = i*16+kq, m = mq*4
    const float* xsrc = x + (size_t)bt * C_DIM * HW + n0;
    const int kq = tid >> 4, mq = tid & 15;
    float4 xr[4];

    auto ldg_x = [&](int kc) {
        #pragma unroll
        for (int i = 0; i < 4; i++) {
            int c = kc * KCH + i * 16 + kq;
            xr[i] = *reinterpret_cast<const float4*>(xsrc + (size_t)c * HW + mq * 4);
        }
    };
    auto sts_x = [&](int buf) {
        uint32_t base = sb + SM_XH + buf * 8192;
        #pragma unroll
        for (int i = 0; i < 4; i++) {
            int k = i * 16 + kq;
            __half2 h0 = __floats2half2_rn(xr[i].x, xr[i].y);
            __half2 h1 = __floats2half2_rn(xr[i].z, xr[i].w);
            uint32_t bo = ((uint32_t)(mq * 8)) ^ (((uint32_t)(k & 7)) << 4);
            STS64(base + (uint32_t)k * 128 + bo, *(uint32_t*)&h0, *(uint32_t*)&h1);
        }
    };

    __syncthreads();   // gg/bias visible; barriers live before waits

    float acc[4][4][4];
    auto zero_acc = [&]() {
        #pragma unroll
        for (int t = 0; t < 4; t++)
            #pragma unroll
            for (int n = 0; n < 4; n++)
                #pragma unroll
                for (int q = 0; q < 4; q++) acc[t][n][q] = 0.f;
    };

    int fullp[NSTAGE] = {0, 0}, emptyp[NSTAGE] = {0, 0};

    // generic chunk: A via non-trans LDSM from aBase ([m][k] 128B rows, 8KB block)
    auto do_chunk = [&](int ci, uint32_t aBase) {
        int j = ci & (NSTAGE - 1);
        MBAR_WAIT(sb + SM_FULL(j), fullp[j]); fullp[j] ^= 1;
        uint32_t bBase = sb + SM_BUFB + j * 32768;
        #pragma unroll
        for (int s = 0; s < 4; s++) {
            uint32_t A[4][4], B[2][4];
            #pragma unroll
            for (int t = 0; t < 4; t++) LDSM4(A[t], aBase + aRow[t] + kAo[s]);
            #pragma unroll
            for (int p = 0; p < 2; p++) LDSM4(B[p], bBase + bRow[p] + kBo[s]);
            #pragma unroll
            for (int t = 0; t < 4; t++)
                #pragma unroll
                for (int n = 0; n < 4; n++)
                    MMA16816(acc[t][n], A[t], B[n >> 1][(n & 1) * 2], B[n >> 1][(n & 1) * 2 + 1]);
        }
        if (lane == 0) MBAR_ARRIVE(sb + SM_EMPTY(j));
        if (tid == 0 && ci + NSTAGE < NCTOT) {
            MBAR_WAIT(sb + SM_EMPTY(j), emptyp[j]); emptyp[j] ^= 1;
            issue(ci + NSTAGE);
        }
    };

    // stage-1 chunk: A via trans LDSM from xh buffer ([k][m] 128B rows)
    auto do_chunk_s1 = [&](int ci, int buf) {
        int j = ci & (NSTAGE - 1);
        MBAR_WAIT(sb + SM_FULL(j), fullp[j]); fullp[j] ^= 1;
        uint32_t bBase = sb + SM_BUFB + j * 32768;
        uint32_t xb = sb + SM_XH + buf * 8192;
        #pragma unroll
        for (int s = 0; s < 4; s++) {
            uint32_t A[4][4], B[2][4];
            uint32_t rbase = xb + (uint32_t)(s * 16 + tRow) * 128;
            #pragma unroll
            for (int t = 0; t < 4; t++) LDSM4T(A[t], rbase + tCol[t]);
            #pragma unroll
            for (int p = 0; p < 2; p++) LDSM4(B[p], bBase + bRow[p] + kBo[s]);
            #pragma unroll
            for (int t = 0; t < 4; t++)
                #pragma unroll
                for (int n = 0; n < 4; n++)
                    MMA16816(acc[t][n], A[t], B[n >> 1][(n & 1) * 2], B[n >> 1][(n & 1) * 2 + 1]);
        }
        if (lane == 0) MBAR_ARRIVE(sb + SM_EMPTY(j));
        if (tid == 0 && ci + NSTAGE < NCTOT) {
            MBAR_WAIT(sb + SM_EMPTY(j), emptyp[j]); emptyp[j] ^= 1;
            issue(ci + NSTAGE);
        }
    };

    // gated-relu -> fp16 -> H (A2 region, 8KB blocks of [64m][64k], SW128)
    auto epi12 = [&](const float* __restrict__ bb) {
        #pragma unroll
        for (int n = 0; n < 4; n++) {
            int c = N0 + n * 8 + 2 * (lane & 3);
            float g0 = gg[c], g1 = gg[c + 1], q0 = bb[c], q1 = bb[c + 1];
            uint32_t base = sb + SM_A2 + (c >> 6) * 8192;
            uint32_t off = (uint32_t)(c & 63) * 2;
            #pragma unroll
            for (int t = 0; t < 4; t++) {
                int r = t * 16 + (lane >> 2);
                __half2 h0 = __floats2half2_rn(g0 * fmaxf(acc[t][n][0] + q0, 0.f),
                                               g1 * fmaxf(acc[t][n][1] + q1, 0.f));
                __half2 h1 = __floats2half2_rn(g0 * fmaxf(acc[t][n][2] + q0, 0.f),
                                               g1 * fmaxf(acc[t][n][3] + q1, 0.f));
                uint32_t bo0 = (uint32_t)r * 128 + off;
                uint32_t bo1 = (uint32_t)(r + 8) * 128 + off;
                STS32(base + SW128(bo0), *(uint32_t*)&h0);
                STS32(base + SW128(bo1), *(uint32_t*)&h1);
            }
        }
    };

    int ci = 0;

    // ---- stage 1: H1 = g*relu(W1 @ x + b1) ----
    zero_acc();
    ldg_x(0); sts_x(0);
    __syncthreads();
    for (int kc = 0; kc < NC1; kc++, ci++) {
        if (kc + 1 < NC1) ldg_x(kc + 1);           // LDG overlaps barrier wait + MMA
        do_chunk_s1(ci, kc & 1);
        if (kc + 1 < NC1) {
            sts_x((kc + 1) & 1);
            __syncthreads();                        // xh[(kc+1)&1] visible to all warps
        }
    }
    __syncthreads();          // all XH reads done before epi12 overwrites alias (A2 blocks 2,3)
    epi12(b1s);
    __syncthreads();

    // ---- stage 2: H2 = g*relu(W2 @ H1 + b2) ----
    zero_acc();
    for (int kc = 0; kc < NC2; kc++, ci++)
        do_chunk(ci, sb + SM_A2 + kc * 8192);
    __syncthreads();          // all H1 reads complete before H2 overwrites A2
    epi12(b2s);
    __syncthreads();

    // ---- stage 3: out = relu(W3 @ H2 + b3) + x ----
    for (int oc = 0; oc < 4; oc++) {
        zero_acc();
        for (int kc = 0; kc < 4; kc++, ci++)
            do_chunk(ci, sb + SM_A2 + kc * 8192);
        #pragma unroll
        for (int n = 0; n < 4; n++) {
            int ch = oc * 256 + N0 + n * 8 + 2 * (lane & 3);
            float q0 = b3s[ch], q1 = b3s[ch + 1];
            size_t gb = ((size_t)(bt * C_DIM + ch)) * HW + n0;
            #pragma unroll
            for (int t = 0; t < 4; t++) {
                int r = t * 16 + (lane >> 2);
                out[gb + r]          = fmaxf(acc[t][n][0] + q0, 0.f) + x[gb + r];
                out[gb + HW + r]     = fmaxf(acc[t][n][1] + q1, 0.f) + x[gb + HW + r];
                out[gb + r + 8]      = fmaxf(acc[t][n][2] + q0, 0.f) + x[gb + r + 8];
                out[gb + HW + r + 8] = fmaxf(acc[t][n][3] + q1, 0.f) + x[gb + HW + r + 8];
            }
        }
    }
}

// ---------------- host side ----------------
typedef CUresult (*PFN_Encode)(CUtensorMap*, CUtensorMapDataType, cuuint32_t, void*,
                               const cuuint64_t*, const cuuint64_t*, const cuuint32_t*,
                               const cuuint32_t*, CUtensorMapInterleave, CUtensorMapSwizzle,
                               CUtensorMapL2promotion, CUtensorMapFloatOOBfill);

static PFN_Encode get_encode_fn() {
    static PFN_Encode fn = nullptr;
    if (!fn) {
        cudaDriverEntryPointQueryResult st;
#if CUDART_VERSION >= 12050
        cudaGetDriverEntryPointByVersion("cuTensorMapEncodeTiled", (void**)&fn, 12000,
                                         cudaEnableDefault, &st);
#else
        cudaGetDriverEntryPoint("cuTensorMapEncodeTiled", (void**)&fn, cudaEnableDefault, &st);
#endif
    }
    return fn;
}

static void make_map(CUtensorMap* m, void* base, uint64_t d0, uint64_t d1,
                     uint64_t rowstride_bytes, uint32_t box0, uint32_t box1) {
    cuuint64_t dims[2] = {d0, d1};
    cuuint64_t strides[1] = {rowstride_bytes};
    cuuint32_t box[2] = {box0, box1};
    cuuint32_t es[2] = {1, 1};
    get_encode_fn()(m, CU_TENSOR_MAP_DATA_TYPE_FLOAT16, 2, base, dims, strides, box, es,
                    CU_TENSOR_MAP_INTERLEAVE_NONE, CU_TENSOR_MAP_SWIZZLE_128B,
                    CU_TENSOR_MAP_L2_PROMOTION_L2_128B, CU_TENSOR_MAP_FLOAT_OOB_FILL_NONE);
}

extern "C" void kernel_launch(void* const* d_in, const int* in_sizes, int n_in,
                              void* d_out, int out_size)
{
    const float* x    = (const float*)d_in[0];
    const float* gate = (const float*)d_in[1];
    const float* W1   = (const float*)d_in[2];
    const float* b1   = (const float*)d_in[3];
    const float* W2   = (const float*)d_in[4];
    const float* b2   = (const float*)d_in[5];
    const float* W3   = (const float*)d_in[6];
    const float* b3   = (const float*)d_in[7];
    float* out        = (float*)d_out;

    void *pW1, *pW2, *pW3;
    cudaGetSymbolAddress(&pW1, g_W1h);
    cudaGetSymbolAddress(&pW2, g_W2h);
    cudaGetSymbolAddress(&pW3, g_W3h);

    CUtensorMap m1, m2, m3;
    make_map(&m1, pW1, C_DIM, MID,   C_DIM * 2, KCH, 256);
    make_map(&m2, pW2, MID,   MID,   MID * 2,   KCH, 256);
    make_map(&m3, pW3, MID,   C_DIM, MID * 2,   KCH, 256);

    cvt_weights<<<(MID * C_DIM + 255) / 256, 256>>>(W1, W2, W3);

    cudaFuncSetAttribute(moe_main, cudaFuncAttributeMaxDynamicSharedMemorySize, SM_TOTAL);
    dim3 grid(NTILE, BATCH);
    moe_main<<<grid, NTHREADS, SM_TOTAL>>>(m1, m2, m3, x, gate, b1, b2, b3, out);
}

// round 17
// speedup vs baseline: 1.4758x; 1.0182x over previous
#include <cuda_runtime.h>
#include <cuda.h>
#include <cuda_fp16.h>
#include <cstdint>

// ---------------- problem constants ----------------
#define C_DIM  1024
#define MID    256
#define BATCH  16
#define HW     3136
#define TILE_M 64
#define NTILE  49          // 3136/64 exact -> no edge guards
#define KCH    64          // K elements per chunk

#define NC1 16             // stage1 K chunks (1024/64)
#define NC2 4              // stage2 (256/64)
#define NC3 16             // stage3: 4 oc blocks x 4 k chunks
#define NCTOT (NC1+NC2+NC3)

#define NTHREADS 128
#define NWARPS   4
#define NSTAGE   2

// ---------------- SMEM layout (bytes) ----------------
#define SM_FULL(j)  ((j)*8)               // 2 x full barriers
#define SM_EMPTY(j) (16 + (j)*8)          // 2 x empty barriers
#define SM_GG   128                       // 256 f32 relu(gate)
#define SM_B1   (SM_GG + 1024)
#define SM_B2   (SM_B1 + 1024)
#define SM_B3   (SM_B2 + 1024)            // 1024 f32
#define SM_A2   8192                      // 4 blocks x 8192: H1/H2 [64m][64k] (aliased)
#define SM_XH   (SM_A2 + 16384)           // ALIAS: x fp16 staging in A2 blocks 2,3
#define SM_BUFB (SM_A2 + 32768)           // 2 x 32768 (weight tiles [256n][64k])
#define SM_TOTAL (SM_BUFB + NSTAGE*32768) // 106496 (104 KB) -> 2 CTAs/SM

// ---------------- device scratch ----------------
__device__ __align__(1024) __half g_W1h[MID * C_DIM];
__device__ __align__(1024) __half g_W2h[MID * MID];
__device__ __align__(1024) __half g_W3h[C_DIM * MID];

// ---------------- ptx helpers (generic PTX only, NO tcgen05) ------
__device__ __forceinline__ uint32_t smem_u32(const void* p) {
    uint32_t a;
    asm("{ .reg .u64 t; cvta.to.shared.u64 t, %1; cvt.u32.u64 %0, t; }" : "=r"(a) : "l"(p));
    return a;
}
#define SW128(bo) ((bo) ^ (((bo) >> 3) & 0x70))

#define MBAR_INIT(a, c) asm volatile("mbarrier.init.shared.b64 [%0], %1;" :: "r"(a), "r"(c) : "memory")
#define MBAR_EXPECT(a, b) asm volatile("mbarrier.arrive.expect_tx.shared.b64 _, [%0], %1;" :: "r"(a), "r"(b) : "memory")
#define MBAR_ARRIVE(a)  asm volatile("mbarrier.arrive.shared.b64 _, [%0];" :: "r"(a) : "memory")
#define MBAR_WAIT(a, p) do { \
    asm volatile("{\n\t.reg .pred P;\n\tWL_%=:\n\t" \
        "mbarrier.try_wait.parity.acquire.cta.shared::cta.b64 P, [%0], %1, 0x989680;\n\t" \
        "@!P bra WL_%=;\n\t}" :: "r"(a), "r"(p) : "memory"); } while (0)

#define TMA2D(sm, mp, cx, cy, mb) \
    asm volatile("cp.async.bulk.tensor.2d.shared::cta.global.tile.mbarrier::complete_tx::bytes " \
                 "[%0], [%1, {%2, %3}], [%4];" \
                 :: "r"(sm), "l"(mp), "r"(cx), "r"(cy), "r"(mb) : "memory")

#define LDSM4(r, addr) \
    asm volatile("ldmatrix.sync.aligned.m8n8.x4.shared.b16 {%0,%1,%2,%3}, [%4];" \
        : "=r"((r)[0]), "=r"((r)[1]), "=r"((r)[2]), "=r"((r)[3]) : "r"(addr))

#define LDSM4T(r, addr) \
    asm volatile("ldmatrix.sync.aligned.m8n8.x4.trans.shared.b16 {%0,%1,%2,%3}, [%4];" \
        : "=r"((r)[0]), "=r"((r)[1]), "=r"((r)[2]), "=r"((r)[3]) : "r"(addr))

#define MMA16816(d, a, b0, b1) \
    asm volatile("mma.sync.aligned.m16n8k16.row.col.f32.f16.f16.f32 " \
        "{%0,%1,%2,%3}, {%4,%5,%6,%7}, {%8,%9}, {%0,%1,%2,%3};" \
        : "+f"((d)[0]), "+f"((d)[1]), "+f"((d)[2]), "+f"((d)[3]) \
        : "r"((a)[0]), "r"((a)[1]), "r"((a)[2]), "r"((a)[3]), "r"(b0), "r"(b1))

#define STS32(a, v) asm volatile("st.shared.b32 [%0], %1;" :: "r"(a), "r"(v) : "memory")
#define STS64(a, v0, v1) asm volatile("st.shared.v2.b32 [%0], {%1, %2};" :: "r"(a), "r"(v0), "r"(v1) : "memory")

// ---------------- pre-pass: weights fp32 -> fp16 ----------------
__global__ void cvt_weights(const float* __restrict__ W1, const float* __restrict__ W2,
                            const float* __restrict__ W3) {
    int i = blockIdx.x * blockDim.x + threadIdx.x;
    if (i < MID * C_DIM) g_W1h[i] = __float2half_rn(W1[i]);
    if (i < MID * MID)   g_W2h[i] = __float2half_rn(W2[i]);
    if (i < C_DIM * MID) g_W3h[i] = __float2half_rn(W3[i]);
}

// ---------------- main fused kernel (4 warps, 2 CTAs/SM) ----------------
__global__ void __launch_bounds__(NTHREADS, 2)
moe_main(const __grid_constant__ CUtensorMap mapW1,
         const __grid_constant__ CUtensorMap mapW2,
         const __grid_constant__ CUtensorMap mapW3,
         const float* __restrict__ x, const float* __restrict__ gate,
         const float* __restrict__ b1, const float* __restrict__ b2,
         const float* __restrict__ b3, float* __restrict__ out)
{
    extern __shared__ __align__(1024) char smem[];
    const uint32_t sb = smem_u32(smem);
    const int tid = threadIdx.x, wid = tid >> 5, lane = tid & 31;
    const int bt = blockIdx.y, nt = blockIdx.x;
    const int n0 = nt * TILE_M;

    const int N0 = wid * 64;             // warp N block (4 in N: 256); M covers all 64
    const int rowin = lane & 7, mat = lane >> 3;
    const uint32_t xorv = (uint32_t)rowin << 4;

    // non-trans ldmatrix addr parts (A [m][k] 128B rows, B [n][k] 128B rows)
    uint32_t aRow[4], bRow[4], kAo[4], kBo[4];
    #pragma unroll
    for (int t = 0; t < 4; t++) aRow[t] = (uint32_t)(t * 16 + (mat & 1) * 8 + rowin) * 128;
    #pragma unroll
    for (int p = 0; p < 4; p++) bRow[p] = (uint32_t)(N0 + p * 16 + (mat >> 1) * 8 + rowin) * 128;
    #pragma unroll
    for (int s = 0; s < 4; s++) {
        kAo[s] = ((uint32_t)(s * 32 + (mat >> 1) * 16)) ^ xorv;
        kBo[s] = ((uint32_t)(s * 32 + (mat & 1) * 16)) ^ xorv;
    }

    // trans ldmatrix addr parts for stage-1 A (xh [k][m] 128B rows)
    const uint32_t tRow = (uint32_t)((mat >> 1) * 8 + rowin);          // 0..15
    uint32_t tCol[4];
    #pragma unroll
    for (int t = 0; t < 4; t++)
        tCol[t] = ((uint32_t)((t * 16) * 2 + (mat & 1) * 16)) ^ xorv;

    if (tid == 0) {
        #pragma unroll
        for (int j = 0; j < NSTAGE; j++) { MBAR_INIT(sb + SM_FULL(j), 1); MBAR_INIT(sb + SM_EMPTY(j), NWARPS); }
    }
    __syncthreads();

    // stage biases / gate into smem
    float* gg  = (float*)(smem + SM_GG);
    float* b1s = (float*)(smem + SM_B1);
    float* b2s = (float*)(smem + SM_B2);
    float* b3s = (float*)(smem + SM_B3);
    for (int i = tid; i < MID; i += NTHREADS) {
        float g = gate[bt * MID + i];
        gg[i]  = g > 0.f ? g : 0.f;
        b1s[i] = b1[i];
        b2s[i] = b2[i];
    }
    for (int i = tid; i < C_DIM; i += NTHREADS) b3s[i] = b3[i];

    auto issue = [&](int ci) {
        int j = ci & (NSTAGE - 1);
        uint32_t fb = sb + SM_FULL(j);
        uint32_t bB = sb + SM_BUFB + j * 32768;
        MBAR_EXPECT(fb, 32768u);
        if (ci < NC1) {
            TMA2D(bB, (const void*)&mapW1, ci * KCH, 0, fb);
        } else if (ci < NC1 + NC2) {
            TMA2D(bB, (const void*)&mapW2, (ci - NC1) * KCH, 0, fb);
        } else {
            int t3 = ci - (NC1 + NC2), oc = t3 >> 2, kc = t3 & 3;
            TMA2D(bB, (const void*)&mapW3, kc * KCH, oc * 256, fb);
        }
    };
    if (tid == 0) { issue(0); issue(1); }

    // ---- stage-1 x: LDG fp32 -> cvt -> xh fp16 [k][m] (64x64, 128B rows) ----
    // 128 threads: kq = tid>>4 (0..7), mq = tid&15; round i: k = i*8+kq, m = mq*4
    const float* xsrc = x + (size_t)bt * C_DIM * HW + n0;
    const int kq = tid >> 4, mq = tid & 15;
    float4 xr[8];

    auto ldg_x = [&](int kc) {
        #pragma unroll
        for (int i = 0; i < 8; i++) {
            int c = kc * KCH + i * 8 + kq;
            xr[i] = *reinterpret_cast<const float4*>(xsrc + (size_t)c * HW + mq * 4);
        }
    };
    auto sts_x = [&](int buf) {
        uint32_t base = sb + SM_XH + buf * 8192;
        #pragma unroll
        for (int i = 0; i < 8; i++) {
            int k = i * 8 + kq;
            __half2 h0 = __floats2half2_rn(xr[i].x, xr[i].y);
            __half2 h1 = __floats2half2_rn(xr[i].z, xr[i].w);
            uint32_t bo = ((uint32_t)(mq * 8)) ^ (((uint32_t)(k & 7)) << 4);
            STS64(base + (uint32_t)k * 128 + bo, *(uint32_t*)&h0, *(uint32_t*)&h1);
        }
    };

    __syncthreads();   // gg/bias visible; barriers live before waits

    float acc[4][8][4];
    auto zero_acc = [&]() {
        #pragma unroll
        for (int t = 0; t < 4; t++)
            #pragma unroll
            for (int n = 0; n < 8; n++)
                #pragma unroll
                for (int q = 0; q < 4; q++) acc[t][n][q] = 0.f;
    };

    int fullp[NSTAGE] = {0, 0}, emptyp[NSTAGE] = {0, 0};

    // generic chunk: A via non-trans LDSM from aBase ([m][k] 128B rows, 8KB block)
    auto do_chunk = [&](int ci, uint32_t aBase) {
        int j = ci & (NSTAGE - 1);
        MBAR_WAIT(sb + SM_FULL(j), fullp[j]); fullp[j] ^= 1;
        uint32_t bBase = sb + SM_BUFB + j * 32768;
        #pragma unroll
        for (int s = 0; s < 4; s++) {
            uint32_t A[4][4], B[4][4];
            #pragma unroll
            for (int t = 0; t < 4; t++) LDSM4(A[t], aBase + aRow[t] + kAo[s]);
            #pragma unroll
            for (int p = 0; p < 4; p++) LDSM4(B[p], bBase + bRow[p] + kBo[s]);
            #pragma unroll
            for (int t = 0; t < 4; t++)
                #pragma unroll
                for (int n = 0; n < 8; n++)
                    MMA16816(acc[t][n], A[t], B[n >> 1][(n & 1) * 2], B[n >> 1][(n & 1) * 2 + 1]);
        }
        if (lane == 0) MBAR_ARRIVE(sb + SM_EMPTY(j));
        if (tid == 0 && ci + NSTAGE < NCTOT) {
            MBAR_WAIT(sb + SM_EMPTY(j), emptyp[j]); emptyp[j] ^= 1;
            issue(ci + NSTAGE);
        }
    };

    // stage-1 chunk: A via trans LDSM from xh buffer ([k][m] 128B rows)
    auto do_chunk_s1 = [&](int ci, int buf) {
        int j = ci & (NSTAGE - 1);
        MBAR_WAIT(sb + SM_FULL(j), fullp[j]); fullp[j] ^= 1;
        uint32_t bBase = sb + SM_BUFB + j * 32768;
        uint32_t xb = sb + SM_XH + buf * 8192;
        #pragma unroll
        for (int s = 0; s < 4; s++) {
            uint32_t A[4][4], B[4][4];
            uint32_t rbase = xb + (uint32_t)(s * 16 + tRow) * 128;
            #pragma unroll
            for (int t = 0; t < 4; t++) LDSM4T(A[t], rbase + tCol[t]);
            #pragma unroll
            for (int p = 0; p < 4; p++) LDSM4(B[p], bBase + bRow[p] + kBo[s]);
            #pragma unroll
            for (int t = 0; t < 4; t++)
                #pragma unroll
                for (int n = 0; n < 8; n++)
                    MMA16816(acc[t][n], A[t], B[n >> 1][(n & 1) * 2], B[n >> 1][(n & 1) * 2 + 1]);
        }
        if (lane == 0) MBAR_ARRIVE(sb + SM_EMPTY(j));
        if (tid == 0 && ci + NSTAGE < NCTOT) {
            MBAR_WAIT(sb + SM_EMPTY(j), emptyp[j]); emptyp[j] ^= 1;
            issue(ci + NSTAGE);
        }
    };

    // gated-relu -> fp16 -> H (A2 region, 8KB blocks of [64m][64k], SW128)
    auto epi12 = [&](const float* __restrict__ bb) {
        #pragma unroll
        for (int n = 0; n < 8; n++) {
            int c = N0 + n * 8 + 2 * (lane & 3);
            float g0 = gg[c], g1 = gg[c + 1], q0 = bb[c], q1 = bb[c + 1];
            uint32_t base = sb + SM_A2 + (c >> 6) * 8192;
            uint32_t off = (uint32_t)(c & 63) * 2;
            #pragma unroll
            for (int t = 0; t < 4; t++) {
                int r = t * 16 + (lane >> 2);
                __half2 h0 = __floats2half2_rn(g0 * fmaxf(acc[t][n][0] + q0, 0.f),
                                               g1 * fmaxf(acc[t][n][1] + q1, 0.f));
                __half2 h1 = __floats2half2_rn(g0 * fmaxf(acc[t][n][2] + q0, 0.f),
                                               g1 * fmaxf(acc[t][n][3] + q1, 0.f));
                uint32_t bo0 = (uint32_t)r * 128 + off;
                uint32_t bo1 = (uint32_t)(r + 8) * 128 + off;
                STS32(base + SW128(bo0), *(uint32_t*)&h0);
                STS32(base + SW128(bo1), *(uint32_t*)&h1);
            }
        }
    };

    int ci = 0;

    // ---- stage 1: H1 = g*relu(W1 @ x + b1) ----
    zero_acc();
    ldg_x(0); sts_x(0);
    __syncthreads();
    for (int kc = 0; kc < NC1; kc++, ci++) {
        if (kc + 1 < NC1) ldg_x(kc + 1);           // LDG overlaps barrier wait + MMA
        do_chunk_s1(ci, kc & 1);
        if (kc + 1 < NC1) {
            sts_x((kc + 1) & 1);
            __syncthreads();                        // xh[(kc+1)&1] visible to all warps
        }
    }
    __syncthreads();          // all XH reads done before epi12 overwrites alias (A2 blocks 2,3)
    epi12(b1s);
    __syncthreads();

    // ---- stage 2: H2 = g*relu(W2 @ H1 + b2) ----
    zero_acc();
    for (int kc = 0; kc < NC2; kc++, ci++)
        do_chunk(ci, sb + SM_A2 + kc * 8192);
    __syncthreads();          // all H1 reads complete before H2 overwrites A2
    epi12(b2s);
    __syncthreads();

    // ---- stage 3: out = relu(W3 @ H2 + b3) + x ----
    for (int oc = 0; oc < 4; oc++) {
        zero_acc();
        for (int kc = 0; kc < 4; kc++, ci++)
            do_chunk(ci, sb + SM_A2 + kc * 8192);
        #pragma unroll
        for (int n = 0; n < 8; n++) {
            int ch = oc * 256 + N0 + n * 8 + 2 * (lane & 3);
            float q0 = b3s[ch], q1 = b3s[ch + 1];
            size_t gb = ((size_t)(bt * C_DIM + ch)) * HW + n0;
            #pragma unroll
            for (int t = 0; t < 4; t++) {
                int r = t * 16 + (lane >> 2);
                out[gb + r]          = fmaxf(acc[t][n][0] + q0, 0.f) + x[gb + r];
                out[gb + HW + r]     = fmaxf(acc[t][n][1] + q1, 0.f) + x[gb + HW + r];
                out[gb + r + 8]      = fmaxf(acc[t][n][2] + q0, 0.f) + x[gb + r + 8];
                out[gb + HW + r + 8] = fmaxf(acc[t][n][3] + q1, 0.f) + x[gb + HW + r + 8];
            }
        }
    }
}

// ---------------- host side ----------------
typedef CUresult (*PFN_Encode)(CUtensorMap*, CUtensorMapDataType, cuuint32_t, void*,
                               const cuuint64_t*, const cuuint64_t*, const cuuint32_t*,
                               const cuuint32_t*, CUtensorMapInterleave, CUtensorMapSwizzle,
                               CUtensorMapL2promotion, CUtensorMapFloatOOBfill);

static PFN_Encode get_encode_fn() {
    static PFN_Encode fn = nullptr;
    if (!fn) {
        cudaDriverEntryPointQueryResult st;
#if CUDART_VERSION >= 12050
        cudaGetDriverEntryPointByVersion("cuTensorMapEncodeTiled", (void**)&fn, 12000,
                                         cudaEnableDefault, &st);
#else
        cudaGetDriverEntryPoint("cuTensorMapEncodeTiled", (void**)&fn, cudaEnableDefault, &st);
#endif
    }
    return fn;
}

static void make_map(CUtensorMap* m, void* base, uint64_t d0, uint64_t d1,
                     uint64_t rowstride_bytes, uint32_t box0, uint32_t box1) {
    cuuint64_t dims[2] = {d0, d1};
    cuuint64_t strides[1] = {rowstride_bytes};
    cuuint32_t box[2] = {box0, box1};
    cuuint32_t es[2] = {1, 1};
    get_encode_fn()(m, CU_TENSOR_MAP_DATA_TYPE_FLOAT16, 2, base, dims, strides, box, es,
                    CU_TENSOR_MAP_INTERLEAVE_NONE, CU_TENSOR_MAP_SWIZZLE_128B,
                    CU_TENSOR_MAP_L2_PROMOTION_L2_128B, CU_TENSOR_MAP_FLOAT_OOB_FILL_NONE);
}

extern "C" void kernel_launch(void* const* d_in, const int* in_sizes, int n_in,
                              void* d_out, int out_size)
{
    const float* x    = (const float*)d_in[0];
    const float* gate = (const float*)d_in[1];
    const float* W1   = (const float*)d_in[2];
    const float* b1   = (const float*)d_in[3];
    const float* W2   = (const float*)d_in[4];
    const float* b2   = (const float*)d_in[5];
    const float* W3   = (const float*)d_in[6];
    const float* b3   = (const float*)d_in[7];
    float* out        = (float*)d_out;

    void *pW1, *pW2, *pW3;
    cudaGetSymbolAddress(&pW1, g_W1h);
    cudaGetSymbolAddress(&pW2, g_W2h);
    cudaGetSymbolAddress(&pW3, g_W3h);

    CUtensorMap m1, m2, m3;
    make_map(&m1, pW1, C_DIM, MID,   C_DIM * 2, KCH, 256);
    make_map(&m2, pW2, MID,   MID,   MID * 2,   KCH, 256);
    make_map(&m3, pW3, MID,   C_DIM, MID * 2,   KCH, 256);

    cvt_weights<<<(MID * C_DIM + 255) / 256, 256>>>(W1, W2, W3);

    cudaFuncSetAttribute(moe_main, cudaFuncAttributeMaxDynamicSharedMemorySize, SM_TOTAL);
    dim3 grid(NTILE, BATCH);
    moe_main<<<grid, NTHREADS, SM_TOTAL>>>(m1, m2, m3, x, gate, b1, b2, b3, out);
}